// round 12
// baseline (speedup 1.0000x reference)
#include <cuda_runtime.h>

// MultiScaleHypercubeLayer fused kernel, R11 (resubmit — round 11 hit a
// GPU-broker acquisition timeout; kernel never measured).
// x: [16384, 2048] f32; W_to: [4,2048]; W_from: [2048,4]; scalars.
//
// vs R7: occupancy play. GRP 8->4 (frees 16 regs) + __launch_bounds__(512,3)
// caps regs at 42 -> 3 CTAs/SM = 48 warps (was 2 CTAs / 32 warps). Phase C
// reloads batched 4-wide to keep MLP under the tighter register budget.
//
// Block = 512 threads = 16 warps, T=16 tokens, two barriers total:
//   Phase A: 4 groups x 4 tokens; batch loads (MLP=4), 6-shuffle reduce.
//   Phase B: warp w computes softmax for token w (16 tokens in parallel).
//   Phase C: 4 groups x 4 tokens; batched L2-hot x reloads + rank-4 epilogue.

#define D_MODEL 2048
#define THREADS 512
#define T 16
#define GRP 4

__global__ void __launch_bounds__(THREADS, 3)
hypercube_kernel(const float* __restrict__ x,
                 const float* __restrict__ W_to,
                 const float* __restrict__ W_from,
                 const float* __restrict__ log_temp,
                 const float* __restrict__ scale_p,
                 float* __restrict__ out)
{
    const int tid  = threadIdx.x;
    const int warp = tid >> 5;
    const int lane = tid & 31;
    const int d0   = tid * 4;

    __shared__ float4 s_part[T][16];  // [token][warp] -> (z0,z1,z2,z3) warp sums
    __shared__ float4 s_q[T];         // scale * quantized / wsum per token

    const float temp  = fminf(fmaxf(expf(__ldg(log_temp)), 0.01f), 5.0f);
    const float inv_t = 1.0f / temp;
    const float scale = __ldg(scale_p);

    const size_t base = (size_t)blockIdx.x * T * D_MODEL + d0;
    const float* xp = x   + base;
    float*       op = out + base;

    // ---- W_to slices in registers (live through Phase A only) ----
    const float4 wt0 = __ldg(reinterpret_cast<const float4*>(W_to + 0 * D_MODEL + d0));
    const float4 wt1 = __ldg(reinterpret_cast<const float4*>(W_to + 1 * D_MODEL + d0));
    const float4 wt2 = __ldg(reinterpret_cast<const float4*>(W_to + 2 * D_MODEL + d0));
    const float4 wt3 = __ldg(reinterpret_cast<const float4*>(W_to + 3 * D_MODEL + d0));

    // ================= Phase A: projections, 4 groups of 4 tokens ============
#pragma unroll
    for (int g = 0; g < T / GRP; g++) {
        float4 xr[GRP];
        // front-batched independent loads: MLP = 4
#pragma unroll
        for (int u = 0; u < GRP; u++)
            xr[u] = *reinterpret_cast<const float4*>(
                xp + (size_t)(g * GRP + u) * D_MODEL);

#pragma unroll
        for (int u = 0; u < GRP; u++) {
            const int t = g * GRP + u;
            const float4 xv = xr[u];

            float z0 = xv.x * wt0.x + xv.y * wt0.y + xv.z * wt0.z + xv.w * wt0.w;
            float z1 = xv.x * wt1.x + xv.y * wt1.y + xv.z * wt1.z + xv.w * wt1.w;
            float z2 = xv.x * wt2.x + xv.y * wt2.y + xv.z * wt2.z + xv.w * wt2.w;
            float z3 = xv.x * wt3.x + xv.y * wt3.y + xv.z * wt3.z + xv.w * wt3.w;

            // transpose-reduce: 6 shuffles.
            float a01 = (lane & 1) ? z1 : z0;
            float b01 = (lane & 1) ? z0 : z1;
            a01 += __shfl_xor_sync(0xffffffffu, b01, 1);
            float a23 = (lane & 1) ? z3 : z2;
            float b23 = (lane & 1) ? z2 : z3;
            a23 += __shfl_xor_sync(0xffffffffu, b23, 1);
            float c = (lane & 2) ? a23 : a01;
            float d = (lane & 2) ? a01 : a23;
            c += __shfl_xor_sync(0xffffffffu, d, 2);
            c += __shfl_xor_sync(0xffffffffu, c, 4);
            c += __shfl_xor_sync(0xffffffffu, c, 8);
            c += __shfl_xor_sync(0xffffffffu, c, 16);

            if (lane < 4)
                reinterpret_cast<float*>(&s_part[t][warp])[lane] = c;
        }
    }
    __syncthreads();

    // ================= Phase B: warp w -> softmax for token w ================
    {
        const int t = warp;
        float4 p = (lane < 16) ? s_part[t][lane]
                               : make_float4(0.f, 0.f, 0.f, 0.f);
#pragma unroll
        for (int off = 1; off <= 8; off <<= 1) {
            p.x += __shfl_xor_sync(0xffffffffu, p.x, off);
            p.y += __shfl_xor_sync(0xffffffffu, p.y, off);
            p.z += __shfl_xor_sync(0xffffffffu, p.z, off);
            p.w += __shfl_xor_sync(0xffffffffu, p.w, off);
        }
        // lane k < 16 owns corner k; V[k][j] = bit (3-j) of k
        const float v0 = (float)((lane >> 3) & 1);
        const float v1 = (float)((lane >> 2) & 1);
        const float v2 = (float)((lane >> 1) & 1);
        const float v3 = (float)(lane & 1);

        const float dx = p.x - v0, dy = p.y - v1, dz = p.z - v2, dw = p.w - v3;
        const float dist = sqrtf(dx * dx + dy * dy + dz * dz + dw * dw);
        // dist >= 0 -> exp(-dist/temp) in (0,1]; no max-subtraction needed.
        float w  = (lane < 16) ? __expf(-dist * inv_t) : 0.f;
        float ws = w;
        float q0 = w * v0, q1 = w * v1, q2 = w * v2, q3 = w * v3;
#pragma unroll
        for (int off = 1; off <= 8; off <<= 1) {
            ws += __shfl_xor_sync(0xffffffffu, ws, off);
            q0 += __shfl_xor_sync(0xffffffffu, q0, off);
            q1 += __shfl_xor_sync(0xffffffffu, q1, off);
            q2 += __shfl_xor_sync(0xffffffffu, q2, off);
            q3 += __shfl_xor_sync(0xffffffffu, q3, off);
        }
        if (lane == 0) {
            const float sc = scale / ws;
            s_q[t] = make_float4(q0 * sc, q1 * sc, q2 * sc, q3 * sc);
        }
    }
    __syncthreads();

    // ================= Phase C: residual + rank-4 epilogue ===================
    // W_from slices loaded here (L2 hits); wt/x-batch registers are dead now.
    const float4 wf0 = __ldg(reinterpret_cast<const float4*>(W_from + (size_t)(d0 + 0) * 4));
    const float4 wf1 = __ldg(reinterpret_cast<const float4*>(W_from + (size_t)(d0 + 1) * 4));
    const float4 wf2 = __ldg(reinterpret_cast<const float4*>(W_from + (size_t)(d0 + 2) * 4));
    const float4 wf3 = __ldg(reinterpret_cast<const float4*>(W_from + (size_t)(d0 + 3) * 4));

#pragma unroll
    for (int g = 0; g < T / GRP; g++) {
        float4 xr[GRP];
        // batched L2/L1-hot reloads: MLP = 4
#pragma unroll
        for (int u = 0; u < GRP; u++)
            xr[u] = *reinterpret_cast<const float4*>(
                xp + (size_t)(g * GRP + u) * D_MODEL);

#pragma unroll
        for (int u = 0; u < GRP; u++) {
            const int t = g * GRP + u;
            const float4 q  = s_q[t];
            const float4 xv = xr[u];
            float4 o;
            o.x = xv.x + q.x * wf0.x + q.y * wf0.y + q.z * wf0.z + q.w * wf0.w;
            o.y = xv.y + q.x * wf1.x + q.y * wf1.y + q.z * wf1.z + q.w * wf1.w;
            o.z = xv.z + q.x * wf2.x + q.y * wf2.y + q.z * wf2.z + q.w * wf2.w;
            o.w = xv.w + q.x * wf3.x + q.y * wf3.y + q.z * wf3.z + q.w * wf3.w;
            *reinterpret_cast<float4*>(op + (size_t)t * D_MODEL) = o;
        }
    }
}

extern "C" void kernel_launch(void* const* d_in, const int* in_sizes, int n_in,
                              void* d_out, int out_size)
{
    const float* x        = (const float*)d_in[0];
    const float* W_to     = (const float*)d_in[1];
    const float* W_from   = (const float*)d_in[2];
    const float* log_temp = (const float*)d_in[3];
    const float* scale    = (const float*)d_in[4];
    float* out = (float*)d_out;

    const int n_tokens = in_sizes[0] / D_MODEL;  // 16384
    const int blocks   = n_tokens / T;           // 1024

    hypercube_kernel<<<blocks, THREADS>>>(x, W_to, W_from, log_temp, scale, out);
}

// round 13
// speedup vs baseline: 1.8310x; 1.8310x over previous
#include <cuda_runtime.h>

// MultiScaleHypercubeLayer fused kernel, R13.
// x: [16384, 2048] f32; W_to: [4,2048]; W_from: [2048,4]; scalars.
//
// vs R11 (regressed: 3 CTAs/SM stretched CTA lifetime -> Phase-C global x
// reload fell out of L2 -> 2.1x DRAM traffic): stage x in SHARED MEMORY so
// the reload can never miss, then keep the 3-CTA occupancy win.
//   T 16->8  => 64 KB dynamic smem stage per CTA; 3 CTAs = ~199 KB/SM.
//   Phase A: 2 groups x 4 tokens; global loads (MLP=4) -> projection + smem stage.
//   Phase B: warp w (w<8) computes softmax for token w.
//   Phase C: x from smem (LDS.128, conflict-free) + rank-4 epilogue -> STG.

#define D_MODEL 2048
#define THREADS 512
#define T 8
#define GRP 4

extern __shared__ float4 s_x[];   // [T * 512] staged x tiles (64 KB)

__global__ void __launch_bounds__(THREADS, 3)
hypercube_kernel(const float* __restrict__ x,
                 const float* __restrict__ W_to,
                 const float* __restrict__ W_from,
                 const float* __restrict__ log_temp,
                 const float* __restrict__ scale_p,
                 float* __restrict__ out)
{
    const int tid  = threadIdx.x;
    const int warp = tid >> 5;
    const int lane = tid & 31;
    const int d0   = tid * 4;

    __shared__ float4 s_part[T][16];  // [token][warp] -> (z0,z1,z2,z3) warp sums
    __shared__ float4 s_q[T];         // scale * quantized / wsum per token

    const float temp  = fminf(fmaxf(expf(__ldg(log_temp)), 0.01f), 5.0f);
    const float inv_t = 1.0f / temp;
    const float scale = __ldg(scale_p);

    const size_t base = (size_t)blockIdx.x * T * D_MODEL + d0;
    const float* xp = x   + base;
    float*       op = out + base;

    // ---- W_to slices in registers (live through Phase A only) ----
    const float4 wt0 = __ldg(reinterpret_cast<const float4*>(W_to + 0 * D_MODEL + d0));
    const float4 wt1 = __ldg(reinterpret_cast<const float4*>(W_to + 1 * D_MODEL + d0));
    const float4 wt2 = __ldg(reinterpret_cast<const float4*>(W_to + 2 * D_MODEL + d0));
    const float4 wt3 = __ldg(reinterpret_cast<const float4*>(W_to + 3 * D_MODEL + d0));

    // ============ Phase A: projections + smem stage, 2 groups of 4 ===========
#pragma unroll
    for (int g = 0; g < T / GRP; g++) {
        float4 xr[GRP];
        // front-batched independent loads: MLP = 4
#pragma unroll
        for (int u = 0; u < GRP; u++)
            xr[u] = *reinterpret_cast<const float4*>(
                xp + (size_t)(g * GRP + u) * D_MODEL);

#pragma unroll
        for (int u = 0; u < GRP; u++) {
            const int t = g * GRP + u;
            const float4 xv = xr[u];

            // stage for Phase C (conflict-free: lane-consecutive 16B)
            s_x[t * THREADS + tid] = xv;

            float z0 = xv.x * wt0.x + xv.y * wt0.y + xv.z * wt0.z + xv.w * wt0.w;
            float z1 = xv.x * wt1.x + xv.y * wt1.y + xv.z * wt1.z + xv.w * wt1.w;
            float z2 = xv.x * wt2.x + xv.y * wt2.y + xv.z * wt2.z + xv.w * wt2.w;
            float z3 = xv.x * wt3.x + xv.y * wt3.y + xv.z * wt3.z + xv.w * wt3.w;

            // transpose-reduce: 6 shuffles.
            float a01 = (lane & 1) ? z1 : z0;
            float b01 = (lane & 1) ? z0 : z1;
            a01 += __shfl_xor_sync(0xffffffffu, b01, 1);
            float a23 = (lane & 1) ? z3 : z2;
            float b23 = (lane & 1) ? z2 : z3;
            a23 += __shfl_xor_sync(0xffffffffu, b23, 1);
            float c = (lane & 2) ? a23 : a01;
            float d = (lane & 2) ? a01 : a23;
            c += __shfl_xor_sync(0xffffffffu, d, 2);
            c += __shfl_xor_sync(0xffffffffu, c, 4);
            c += __shfl_xor_sync(0xffffffffu, c, 8);
            c += __shfl_xor_sync(0xffffffffu, c, 16);

            if (lane < 4)
                reinterpret_cast<float*>(&s_part[t][warp])[lane] = c;
        }
    }
    __syncthreads();

    // ============ Phase B: warp w (<T) -> softmax for token w ================
    if (warp < T) {
        const int t = warp;
        float4 p = (lane < 16) ? s_part[t][lane]
                               : make_float4(0.f, 0.f, 0.f, 0.f);
#pragma unroll
        for (int off = 1; off <= 8; off <<= 1) {
            p.x += __shfl_xor_sync(0xffffffffu, p.x, off);
            p.y += __shfl_xor_sync(0xffffffffu, p.y, off);
            p.z += __shfl_xor_sync(0xffffffffu, p.z, off);
            p.w += __shfl_xor_sync(0xffffffffu, p.w, off);
        }
        // lane k < 16 owns corner k; V[k][j] = bit (3-j) of k
        const float v0 = (float)((lane >> 3) & 1);
        const float v1 = (float)((lane >> 2) & 1);
        const float v2 = (float)((lane >> 1) & 1);
        const float v3 = (float)(lane & 1);

        const float dx = p.x - v0, dy = p.y - v1, dz = p.z - v2, dw = p.w - v3;
        const float dist = sqrtf(dx * dx + dy * dy + dz * dz + dw * dw);
        // dist >= 0 -> exp(-dist/temp) in (0,1]; no max-subtraction needed.
        float w  = (lane < 16) ? __expf(-dist * inv_t) : 0.f;
        float ws = w;
        float q0 = w * v0, q1 = w * v1, q2 = w * v2, q3 = w * v3;
#pragma unroll
        for (int off = 1; off <= 8; off <<= 1) {
            ws += __shfl_xor_sync(0xffffffffu, ws, off);
            q0 += __shfl_xor_sync(0xffffffffu, q0, off);
            q1 += __shfl_xor_sync(0xffffffffu, q1, off);
            q2 += __shfl_xor_sync(0xffffffffu, q2, off);
            q3 += __shfl_xor_sync(0xffffffffu, q3, off);
        }
        if (lane == 0) {
            const float sc = scale / ws;
            s_q[t] = make_float4(q0 * sc, q1 * sc, q2 * sc, q3 * sc);
        }
    }
    __syncthreads();

    // ============ Phase C: residual + rank-4 epilogue (x from smem) ==========
    const float4 wf0 = __ldg(reinterpret_cast<const float4*>(W_from + (size_t)(d0 + 0) * 4));
    const float4 wf1 = __ldg(reinterpret_cast<const float4*>(W_from + (size_t)(d0 + 1) * 4));
    const float4 wf2 = __ldg(reinterpret_cast<const float4*>(W_from + (size_t)(d0 + 2) * 4));
    const float4 wf3 = __ldg(reinterpret_cast<const float4*>(W_from + (size_t)(d0 + 3) * 4));

#pragma unroll
    for (int t = 0; t < T; t++) {
        const float4 q  = s_q[t];
        const float4 xv = s_x[t * THREADS + tid];
        float4 o;
        o.x = xv.x + q.x * wf0.x + q.y * wf0.y + q.z * wf0.z + q.w * wf0.w;
        o.y = xv.y + q.x * wf1.x + q.y * wf1.y + q.z * wf1.z + q.w * wf1.w;
        o.z = xv.z + q.x * wf2.x + q.y * wf2.y + q.z * wf2.z + q.w * wf2.w;
        o.w = xv.w + q.x * wf3.x + q.y * wf3.y + q.z * wf3.z + q.w * wf3.w;
        *reinterpret_cast<float4*>(op + (size_t)t * D_MODEL) = o;
    }
}

extern "C" void kernel_launch(void* const* d_in, const int* in_sizes, int n_in,
                              void* d_out, int out_size)
{
    const float* x        = (const float*)d_in[0];
    const float* W_to     = (const float*)d_in[1];
    const float* W_from   = (const float*)d_in[2];
    const float* log_temp = (const float*)d_in[3];
    const float* scale    = (const float*)d_in[4];
    float* out = (float*)d_out;

    const int n_tokens = in_sizes[0] / D_MODEL;  // 16384
    const int blocks   = n_tokens / T;           // 2048
    const int smem     = T * D_MODEL * sizeof(float);  // 64 KB dynamic

    // Deterministic, host-side, capture-safe; needed for >48 KB dynamic smem.
    cudaFuncSetAttribute(hypercube_kernel,
                         cudaFuncAttributeMaxDynamicSharedMemorySize, smem);

    hypercube_kernel<<<blocks, THREADS, smem>>>(x, W_to, W_from, log_temp,
                                                scale, out);
}

// round 14
// speedup vs baseline: 2.4449x; 1.3353x over previous
#include <cuda_runtime.h>

// MultiScaleHypercubeLayer fused kernel, R14.
// x: [16384, 2048] f32; W_to: [4,2048]; W_from: [2048,4]; scalars.
//
// vs R13: software-pipelined groups so the DRAM read stream (next group's
// prefetch, issued BEFORE the barrier) overlaps the write stream (current
// group's epilogue stores). Fixes the phase-split ~50% DRAM cap seen in all
// prior rounds (reads only in A, writes only in C, never concurrent).
//
// Block = 512 threads = 16 warps, T=16 tokens in NB=4 groups of G=4:
//   per group: proj+stage (smem, thread-private slots) -> prefetch next group's
//   LDGs -> bar -> softmax (warps 0-3) -> bar -> epilogue from smem + STG.
// wt/wf/xr in registers; __launch_bounds__(512,2) (~60 regs).

#define D_MODEL 2048
#define THREADS 512
#define G 4
#define NB 4
#define T (G * NB)

extern __shared__ float4 s_x[];   // [G * THREADS] staged x (32 KB), reused per group

__global__ void __launch_bounds__(THREADS, 2)
hypercube_kernel(const float* __restrict__ x,
                 const float* __restrict__ W_to,
                 const float* __restrict__ W_from,
                 const float* __restrict__ log_temp,
                 const float* __restrict__ scale_p,
                 float* __restrict__ out)
{
    const int tid  = threadIdx.x;
    const int warp = tid >> 5;
    const int lane = tid & 31;
    const int d0   = tid * 4;

    __shared__ float4 s_part[G][16];  // [token-in-group][warp] partial z
    __shared__ float4 s_q[G];         // scale * quantized / wsum per token

    const float temp  = fminf(fmaxf(expf(__ldg(log_temp)), 0.01f), 5.0f);
    const float inv_t = 1.0f / temp;
    const float scale = __ldg(scale_p);

    const size_t base = (size_t)blockIdx.x * T * D_MODEL + d0;
    const float* xp = x   + base;
    float*       op = out + base;

    // ---- weights resident in registers ----
    const float4 wt0 = __ldg(reinterpret_cast<const float4*>(W_to + 0 * D_MODEL + d0));
    const float4 wt1 = __ldg(reinterpret_cast<const float4*>(W_to + 1 * D_MODEL + d0));
    const float4 wt2 = __ldg(reinterpret_cast<const float4*>(W_to + 2 * D_MODEL + d0));
    const float4 wt3 = __ldg(reinterpret_cast<const float4*>(W_to + 3 * D_MODEL + d0));

    const float4 wf0 = __ldg(reinterpret_cast<const float4*>(W_from + (size_t)(d0 + 0) * 4));
    const float4 wf1 = __ldg(reinterpret_cast<const float4*>(W_from + (size_t)(d0 + 1) * 4));
    const float4 wf2 = __ldg(reinterpret_cast<const float4*>(W_from + (size_t)(d0 + 2) * 4));
    const float4 wf3 = __ldg(reinterpret_cast<const float4*>(W_from + (size_t)(d0 + 3) * 4));

    // ---- prefetch group 0 ----
    float4 xr[G];
#pragma unroll
    for (int u = 0; u < G; u++)
        xr[u] = *reinterpret_cast<const float4*>(xp + (size_t)u * D_MODEL);

#pragma unroll
    for (int g = 0; g < NB; g++) {
        // ---- projection + smem stage for current group ----
#pragma unroll
        for (int u = 0; u < G; u++) {
            const float4 xv = xr[u];
            s_x[u * THREADS + tid] = xv;   // thread-private slot, reused per group

            float z0 = xv.x * wt0.x + xv.y * wt0.y + xv.z * wt0.z + xv.w * wt0.w;
            float z1 = xv.x * wt1.x + xv.y * wt1.y + xv.z * wt1.z + xv.w * wt1.w;
            float z2 = xv.x * wt2.x + xv.y * wt2.y + xv.z * wt2.z + xv.w * wt2.w;
            float z3 = xv.x * wt3.x + xv.y * wt3.y + xv.z * wt3.z + xv.w * wt3.w;

            // transpose-reduce: 6 shuffles.
            float a01 = (lane & 1) ? z1 : z0;
            float b01 = (lane & 1) ? z0 : z1;
            a01 += __shfl_xor_sync(0xffffffffu, b01, 1);
            float a23 = (lane & 1) ? z3 : z2;
            float b23 = (lane & 1) ? z2 : z3;
            a23 += __shfl_xor_sync(0xffffffffu, b23, 1);
            float c = (lane & 2) ? a23 : a01;
            float d = (lane & 2) ? a01 : a23;
            c += __shfl_xor_sync(0xffffffffu, d, 2);
            c += __shfl_xor_sync(0xffffffffu, c, 4);
            c += __shfl_xor_sync(0xffffffffu, c, 8);
            c += __shfl_xor_sync(0xffffffffu, c, 16);

            if (lane < 4)
                reinterpret_cast<float*>(&s_part[u][warp])[lane] = c;
        }

        // ---- issue next group's loads NOW: in flight across both barriers,
        //      the softmax, and this group's epilogue stores (read/write overlap)
        if (g + 1 < NB) {
#pragma unroll
            for (int u = 0; u < G; u++)
                xr[u] = *reinterpret_cast<const float4*>(
                    xp + (size_t)((g + 1) * G + u) * D_MODEL);
        }

        __syncthreads();

        // ---- softmax: warp u (<G) handles token u of this group ----
        if (warp < G) {
            float4 p = (lane < 16) ? s_part[warp][lane]
                                   : make_float4(0.f, 0.f, 0.f, 0.f);
#pragma unroll
            for (int off = 1; off <= 8; off <<= 1) {
                p.x += __shfl_xor_sync(0xffffffffu, p.x, off);
                p.y += __shfl_xor_sync(0xffffffffu, p.y, off);
                p.z += __shfl_xor_sync(0xffffffffu, p.z, off);
                p.w += __shfl_xor_sync(0xffffffffu, p.w, off);
            }
            // lane k < 16 owns corner k; V[k][j] = bit (3-j) of k
            const float v0 = (float)((lane >> 3) & 1);
            const float v1 = (float)((lane >> 2) & 1);
            const float v2 = (float)((lane >> 1) & 1);
            const float v3 = (float)(lane & 1);

            const float dx = p.x - v0, dy = p.y - v1, dz = p.z - v2, dw = p.w - v3;
            const float dist = sqrtf(dx * dx + dy * dy + dz * dz + dw * dw);
            float w  = (lane < 16) ? __expf(-dist * inv_t) : 0.f;
            float ws = w;
            float q0 = w * v0, q1 = w * v1, q2 = w * v2, q3 = w * v3;
#pragma unroll
            for (int off = 1; off <= 8; off <<= 1) {
                ws += __shfl_xor_sync(0xffffffffu, ws, off);
                q0 += __shfl_xor_sync(0xffffffffu, q0, off);
                q1 += __shfl_xor_sync(0xffffffffu, q1, off);
                q2 += __shfl_xor_sync(0xffffffffu, q2, off);
                q3 += __shfl_xor_sync(0xffffffffu, q3, off);
            }
            if (lane == 0) {
                const float sc = scale / ws;
                s_q[warp] = make_float4(q0 * sc, q1 * sc, q2 * sc, q3 * sc);
            }
        }
        __syncthreads();

        // ---- epilogue: x from smem stage, rank-4 expansion, store ----
#pragma unroll
        for (int u = 0; u < G; u++) {
            const float4 q  = s_q[u];
            const float4 xv = s_x[u * THREADS + tid];
            float4 o;
            o.x = xv.x + q.x * wf0.x + q.y * wf0.y + q.z * wf0.z + q.w * wf0.w;
            o.y = xv.y + q.x * wf1.x + q.y * wf1.y + q.z * wf1.z + q.w * wf1.w;
            o.z = xv.z + q.x * wf2.x + q.y * wf2.y + q.z * wf2.z + q.w * wf2.w;
            o.w = xv.w + q.x * wf3.x + q.y * wf3.y + q.z * wf3.z + q.w * wf3.w;
            *reinterpret_cast<float4*>(op + (size_t)(g * G + u) * D_MODEL) = o;
        }
    }
}

extern "C" void kernel_launch(void* const* d_in, const int* in_sizes, int n_in,
                              void* d_out, int out_size)
{
    const float* x        = (const float*)d_in[0];
    const float* W_to     = (const float*)d_in[1];
    const float* W_from   = (const float*)d_in[2];
    const float* log_temp = (const float*)d_in[3];
    const float* scale    = (const float*)d_in[4];
    float* out = (float*)d_out;

    const int n_tokens = in_sizes[0] / D_MODEL;            // 16384
    const int blocks   = n_tokens / T;                     // 1024
    const int smem     = G * THREADS * sizeof(float4);     // 32 KB dynamic

    cudaFuncSetAttribute(hypercube_kernel,
                         cudaFuncAttributeMaxDynamicSharedMemorySize, smem);

    hypercube_kernel<<<blocks, THREADS, smem>>>(x, W_to, W_from, log_temp,
                                                scale, out);
}